// round 16
// baseline (speedup 1.0000x reference)
#include <cuda_runtime.h>
#include <cuda_fp16.h>
#include <cstdint>

// ---------------------------------------------------------------------------
// Problem constants
// ---------------------------------------------------------------------------
#define D_IN   128
#define WID    512
#define NSEG   256
#define HEADS  8
#define DPD    128
#define COMB   (D_IN + WID)
#define RCP_TAB 4096
#define NMAX 131072

// ---------------------------------------------------------------------------
// Device global scratch (no runtime allocation)
// ---------------------------------------------------------------------------
__device__ __half g_x16[(size_t)NMAX * D_IN];
__device__ __half g_hA[(size_t)NMAX * WID];
__device__ __half g_hB[(size_t)NMAX * WID];
__device__ __half g_z16[(size_t)NMAX * WID];
__device__ __half g_agg16[(size_t)NMAX * WID];
__device__ __half g_w1t[WID * D_IN];
__device__ __half g_w2t[WID * WID];
__device__ __half g_w3t[WID * WID];
__device__ __half g_wrt[WID * WID];
__device__ float g_weff[COMB * HEADS];
__device__ int   g_segstart[NSEG + 1];
__device__ float g_rcp[RCP_TAB];

// ---------------------------------------------------------------------------
// PTX primitives (non-arch-specific; valid on plain sm_100)
// ---------------------------------------------------------------------------
__device__ __forceinline__ uint32_t smem_u32(const void* p) {
    uint32_t a;
    asm("{ .reg .u64 t; cvta.to.shared.u64 t, %1; cvt.u32.u64 %0, t; }" : "=r"(a) : "l"(p));
    return a;
}

#define CP_ASYNC16(dst, src) \
    asm volatile("cp.async.cg.shared.global [%0], [%1], 16;" :: "r"(dst), "l"(src))
#define CP_COMMIT() asm volatile("cp.async.commit_group;" ::: "memory")
#define CP_WAIT1()  asm volatile("cp.async.wait_group 1;" ::: "memory")
#define CP_WAIT0()  asm volatile("cp.async.wait_group 0;" ::: "memory")

#define LDSM_X4(r, addr) \
    asm volatile("ldmatrix.sync.aligned.m8n8.x4.shared.b16 {%0,%1,%2,%3}, [%4];" \
        : "=r"((r)[0]), "=r"((r)[1]), "=r"((r)[2]), "=r"((r)[3]) : "r"(addr))

// fp16 MMA m16n8k16, fp32 accum
__device__ __forceinline__ void mma_f16(float* d, const uint32_t* a, uint32_t b0, uint32_t b1) {
    asm volatile(
        "mma.sync.aligned.m16n8k16.row.col.f32.f16.f16.f32 "
        "{%0,%1,%2,%3}, {%4,%5,%6,%7}, {%8,%9}, {%0,%1,%2,%3};"
        : "+f"(d[0]), "+f"(d[1]), "+f"(d[2]), "+f"(d[3])
        : "r"(a[0]), "r"(a[1]), "r"(a[2]), "r"(a[3]), "r"(b0), "r"(b1));
}

// ---------------------------------------------------------------------------
// Small precompute kernels
// ---------------------------------------------------------------------------
__global__ void segstart_kernel(const int* __restrict__ segw, int M) {
    int s = threadIdx.x;
    if (s > NSEG) return;
    bool is64 = (segw[M - 1] == 0);   // int64: high half of last elem is 0
    int lo = 0, hi = M;
    while (lo < hi) {
        int mid = (lo + hi) >> 1;
        int v = is64 ? segw[2 * mid] : segw[mid];
        if (v < s) lo = mid + 1; else hi = mid;
    }
    g_segstart[s] = lo;
}

__global__ void rcp_init_kernel() {
    int i = blockIdx.x * blockDim.x + threadIdx.x;
    if (i < RCP_TAB) g_rcp[i] = 1.0f / (float)(i ? i : 1);
}

__global__ void weff_kernel(const float* __restrict__ Wk, const float* __restrict__ Wq) {
    int idx = blockIdx.x * blockDim.x + threadIdx.x;
    if (idx >= COMB * HEADS) return;
    int j = idx >> 3, h = idx & 7;
    const float* wk = Wk + (size_t)j * (HEADS * DPD) + h * DPD;
    const float* wq = Wq + h * DPD;
    float s = 0.f;
    #pragma unroll 8
    for (int d = 0; d < DPD; d++) s += wk[d] * wq[d];
    g_weff[idx] = s;
}

// X fp32 -> fp16 (vectorized)
__global__ void xcvt_kernel(const float* __restrict__ X, __half* __restrict__ O, size_t n4) {
    size_t i = (size_t)blockIdx.x * blockDim.x + threadIdx.x;
    if (i >= n4) return;
    float4 v = ((const float4*)X)[i];
    ((__half2*)O)[2 * i]     = __floats2half2_rn(v.x, v.y);
    ((__half2*)O)[2 * i + 1] = __floats2half2_rn(v.z, v.w);
}

// W [K, 512] fp32 -> Wt [512, K] fp16 (transpose + convert)
__global__ void wcvt_kernel(const float* __restrict__ W, __half* __restrict__ Wt, int K) {
    int i = blockIdx.x * blockDim.x + threadIdx.x;
    if (i >= WID * K) return;
    int n = i / K, k = i % K;
    Wt[i] = __float2half(W[(size_t)k * WID + n]);
}

// ---------------------------------------------------------------------------
// fp16 GEMM on mma.sync m16n8k16 (fp32 accum).
//   CTA tile 128x128, 8 warps (4m x 2n), warp tile 32x64.
//   K-chunk 64 elems (128B rows, TS_B=144 -> ldsm banks 4i..4i+3 conflict-free),
//   3-stage cp.async ring with WAIT1 + issue-ahead (Round-13 policy, halved
//   barrier count). Rolling B-fragment double buffer across the 4 k16 steps.
//   MODE 0: Oh = fp16(relu(D + bias)) ; MODE 1: Oh = fp16(D)
// ---------------------------------------------------------------------------
#define TS_B      144
#define T128_B    (128 * TS_B)              // 18432 per operand tile
#define ST_A      0
#define ST_B      (T128_B)
#define STAGE_B   (2 * T128_B)              // 36864
#define NSTAGE    3
#define GEMM_SMEM (NSTAGE * STAGE_B)        // 110592
#define EPI_STW   136                       // fp16 stride (272 B) for staging

template<int MODE>
__global__ __launch_bounds__(256, 2)
void f16_gemm(const __half* __restrict__ A, const __half* __restrict__ B,
              const float* __restrict__ bias, __half* __restrict__ Oh, int K) {
    extern __shared__ char smem[];
    const uint32_t sb = smem_u32(smem);

    const int tid    = threadIdx.x;
    const int wid    = tid >> 5;
    const int lane   = tid & 31;
    const int warp_m = wid >> 1;          // 0..3 -> m offset 32*warp_m
    const int warp_n = wid & 1;           // 0..1 -> n offset 64*warp_n
    const int m0 = blockIdx.y * 128;      // x fastest -> A panel shared in L2
    const int n0 = blockIdx.x * 128;

    // ---- load setup: 2 threads per 128B row; 4x16B consecutive each ------
    const int lr = tid >> 1;              // 0..127 row
    const int lj = (tid & 1) * 64;        // byte offset within row (0 or 64)
    const __half* pA = A + (size_t)(m0 + lr) * K + lj / 2;
    const __half* pB = B + (size_t)(n0 + lr) * K + lj / 2;
    const uint32_t dA0 = (uint32_t)(ST_A + lr * TS_B + lj);
    const uint32_t dB0 = (uint32_t)(ST_B + lr * TS_B + lj);

    // ---- compute setup ----
    const int lrow = lane & 15;
    const int lchk = (lane >> 4) * 16;
    const uint32_t aoff = (uint32_t)((warp_m * 32 + lrow) * TS_B + lchk);
    const uint32_t boff = (uint32_t)((warp_n * 64 + lrow) * TS_B + lchk);

    float acc[2][8][4];                   // [mb 16][nb n8][frag]
    #pragma unroll
    for (int i = 0; i < 2; i++)
        #pragma unroll
        for (int j = 0; j < 8; j++)
            #pragma unroll
            for (int q = 0; q < 4; q++) acc[i][j][q] = 0.f;

    const int nch = K >> 6;               // 64-elem chunks

    #define ISSUE_CHUNK(stg) do {                          \
        uint32_t _b = sb + (stg) * STAGE_B;                \
        CP_ASYNC16(_b + dA0,      pA);                     \
        CP_ASYNC16(_b + dA0 + 16, pA + 8);                 \
        CP_ASYNC16(_b + dA0 + 32, pA + 16);                \
        CP_ASYNC16(_b + dA0 + 48, pA + 24);                \
        CP_ASYNC16(_b + dB0,      pB);                     \
        CP_ASYNC16(_b + dB0 + 16, pB + 8);                 \
        CP_ASYNC16(_b + dB0 + 32, pB + 16);                \
        CP_ASYNC16(_b + dB0 + 48, pB + 24);                \
        pA += 64; pB += 64;                                \
        CP_COMMIT();                                       \
    } while (0)

    ISSUE_CHUNK(0);
    if (nch > 1) ISSUE_CHUNK(1);

    int stg = 0;
    for (int c = 0; c < nch; c++) {
        if (c + 1 < nch) CP_WAIT1(); else CP_WAIT0();
        __syncthreads();                  // single sync per 64-elem chunk
        if (c + 2 < nch) {
            int ns = stg + 2; if (ns >= NSTAGE) ns -= NSTAGE;
            ISSUE_CHUNK(ns);
        }

        const uint32_t stage = sb + stg * STAGE_B;
        const uint32_t sA = stage + ST_A + aoff;
        const uint32_t sB_ = stage + ST_B + boff;

        uint32_t bh[2][4][4], af[2][4];
        // preload ks=0 fragments
        #pragma unroll
        for (int g = 0; g < 4; g++)
            LDSM_X4(bh[0][g], sB_ + g * (16 * TS_B));
        #pragma unroll
        for (int mb = 0; mb < 2; mb++)
            LDSM_X4(af[mb], sA + mb * (16 * TS_B));

        #pragma unroll
        for (int ks = 0; ks < 4; ks++) {
            // prefetch next-step B fragments under this step's MMAs
            if (ks < 3) {
                #pragma unroll
                for (int g = 0; g < 4; g++)
                    LDSM_X4(bh[(ks + 1) & 1][g], sB_ + g * (16 * TS_B) + (ks + 1) * 32);
            }
            #pragma unroll
            for (int mb = 0; mb < 2; mb++)
                #pragma unroll
                for (int nb = 0; nb < 8; nb++) {
                    const int g = nb >> 1, p = nb & 1;
                    mma_f16(acc[mb][nb], af[mb], bh[ks & 1][g][p], bh[ks & 1][g][p + 2]);
                }
            if (ks < 3) {
                #pragma unroll
                for (int mb = 0; mb < 2; mb++)
                    LDSM_X4(af[mb], sA + mb * (16 * TS_B) + (ks + 1) * 32);
            }
        }

        if (++stg == NSTAGE) stg = 0;
    }
    #undef ISSUE_CHUNK

    // ---------------- Epilogue (smem-staged, coalesced fp16 stores) --------
    const int gid  = lane >> 2;
    const int tid4 = lane & 3;

    __syncthreads();                      // mainloop done; reuse stage smem
    __half* sh = (__half*)smem;

    #pragma unroll
    for (int nb = 0; nb < 8; nb++) {
        const int cc  = warp_n * 64 + nb * 8 + tid4 * 2;
        const int col = n0 + cc;
        float b0 = 0.f, b1 = 0.f;
        if (MODE == 0) { b0 = bias[col]; b1 = bias[col + 1]; }
        #pragma unroll
        for (int mb = 0; mb < 2; mb++) {
            #pragma unroll
            for (int half = 0; half < 2; half++) {
                const int r = warp_m * 32 + mb * 16 + gid + half * 8;
                float d0 = acc[mb][nb][2 * half];
                float d1 = acc[mb][nb][2 * half + 1];
                if (MODE == 0) {
                    d0 = fmaxf(d0 + b0, 0.f);
                    d1 = fmaxf(d1 + b1, 0.f);
                }
                *(__half2*)(sh + r * EPI_STW + cc) = __floats2half2_rn(d0, d1);
            }
        }
    }
    __syncthreads();

    // copy-out: warp owns 16 rows; per iter 2 rows x 16 chunks of 16B
    const int rhalf = lane >> 4;          // 0..1
    const int c16   = lane & 15;          // 16B chunk in 256B row
    #pragma unroll
    for (int it = 0; it < 8; it++) {
        const int r = wid * 16 + it * 2 + rhalf;
        const uint4 vh = *(const uint4*)(sh + r * EPI_STW + c16 * 8);
        const size_t gbase = (size_t)(m0 + r) * WID + n0 + c16 * 8;
        *(uint4*)(Oh + gbase) = vh;
    }
}

// ---------------------------------------------------------------------------
// Segmented prefix-mean + bias + relu (z fp16 -> agg fp16; fp32 accumulate)
// ---------------------------------------------------------------------------
__global__ void scan_kernel(const __half* __restrict__ Z, const float* __restrict__ br,
                            __half* __restrict__ Agg) {
    int seg = blockIdx.x;
    int col = blockIdx.y * blockDim.x + threadIdx.x;
    int s = g_segstart[seg];
    int e = g_segstart[seg + 1];
    float b = br[col];
    float run = 0.f;
    for (int n = s; n < e; n++) {
        run += __half2float(Z[(size_t)n * WID + col]);
        int cnt = n - s + 1;
        float m = (cnt < RCP_TAB) ? run * g_rcp[cnt] : run / (float)cnt;
        Agg[(size_t)n * WID + col] = __float2half(fmaxf(m + b, 0.f));
    }
}

// ---------------------------------------------------------------------------
// Final projection: out[n,h] = ([X, agg] @ w_eff)[n,h] / sqrt(DPD)
// (reads fp16 X and fp16 agg)
// ---------------------------------------------------------------------------
__global__ __launch_bounds__(256)
void final_kernel(const __half* __restrict__ X16, const __half* __restrict__ Agg,
                  float* __restrict__ out, int M) {
    __shared__ float ws[HEADS * COMB];
    for (int i = threadIdx.x; i < COMB * HEADS; i += blockDim.x) {
        int j = i >> 3, h = i & 7;
        ws[h * COMB + j] = g_weff[i];
    }
    __syncthreads();

    int warp = threadIdx.x >> 5;
    int lane = threadIdx.x & 31;
    int row  = blockIdx.x * 8 + warp;
    if (row >= M) return;

    const __half* xr = X16 + (size_t)row * D_IN;
    const __half* ar = Agg + (size_t)row * WID;

    float acc[HEADS];
    #pragma unroll
    for (int h = 0; h < HEADS; h++) acc[h] = 0.f;

    #pragma unroll
    for (int t = 0; t < D_IN / 32; t++) {
        int j = t * 32 + lane;
        float v = __half2float(xr[j]);
        #pragma unroll
        for (int h = 0; h < HEADS; h++) acc[h] = fmaf(v, ws[h * COMB + j], acc[h]);
    }
    #pragma unroll
    for (int t = 0; t < WID / 32; t++) {
        int j = t * 32 + lane;
        float v = __half2float(ar[j]);
        #pragma unroll
        for (int h = 0; h < HEADS; h++) acc[h] = fmaf(v, ws[h * COMB + D_IN + j], acc[h]);
    }

    #pragma unroll
    for (int off = 16; off; off >>= 1)
        #pragma unroll
        for (int h = 0; h < HEADS; h++)
            acc[h] += __shfl_xor_sync(0xffffffffu, acc[h], off);

    if (lane < HEADS)
        out[(size_t)row * HEADS + lane] = acc[lane] * 0.08838834764831844f;
}

// ---------------------------------------------------------------------------
// Launch
// ---------------------------------------------------------------------------
extern "C" void kernel_launch(void* const* d_in, const int* in_sizes, int n_in,
                              void* d_out, int out_size) {
    const float* X   = (const float*)d_in[0];
    const int*   seg = (const int*)  d_in[1];
    const float* W1  = (const float*)d_in[2];
    const float* b1  = (const float*)d_in[3];
    const float* W2  = (const float*)d_in[4];
    const float* b2  = (const float*)d_in[5];
    const float* W3  = (const float*)d_in[6];
    const float* b3  = (const float*)d_in[7];
    const float* Wr  = (const float*)d_in[8];
    const float* br  = (const float*)d_in[9];
    const float* Wk  = (const float*)d_in[10];
    const float* Wq  = (const float*)d_in[11];
    float* out = (float*)d_out;

    const int M = in_sizes[0] / D_IN;

    __half *x16, *hA, *hB, *z16, *agg16, *w1t, *w2t, *w3t, *wrt;
    cudaGetSymbolAddress((void**)&x16, g_x16);
    cudaGetSymbolAddress((void**)&hA,  g_hA);
    cudaGetSymbolAddress((void**)&hB,  g_hB);
    cudaGetSymbolAddress((void**)&z16, g_z16);
    cudaGetSymbolAddress((void**)&agg16, g_agg16);
    cudaGetSymbolAddress((void**)&w1t, g_w1t);
    cudaGetSymbolAddress((void**)&w2t, g_w2t);
    cudaGetSymbolAddress((void**)&w3t, g_w3t);
    cudaGetSymbolAddress((void**)&wrt, g_wrt);

    cudaFuncSetAttribute(f16_gemm<0>, cudaFuncAttributeMaxDynamicSharedMemorySize, GEMM_SMEM);
    cudaFuncSetAttribute(f16_gemm<1>, cudaFuncAttributeMaxDynamicSharedMemorySize, GEMM_SMEM);

    const dim3 ggrid(WID / 128, M / 128);  // x fastest: 4 N-blocks share an A panel

    xcvt_kernel<<<(unsigned)(((size_t)M * D_IN / 4 + 255) / 256), 256>>>(X, x16, (size_t)M * D_IN / 4);
    wcvt_kernel<<<(WID * D_IN + 255) / 256, 256>>>(W1, w1t, D_IN);
    rcp_init_kernel<<<RCP_TAB / 256, 256>>>();

    // h1 = relu(X @ W1 + b1)
    f16_gemm<0><<<ggrid, 256, GEMM_SMEM>>>(x16, w1t, b1, hA, D_IN);
    wcvt_kernel<<<(WID * WID + 255) / 256, 256>>>(W2, w2t, WID);

    // h2 = relu(h1 @ W2 + b2)
    f16_gemm<0><<<ggrid, 256, GEMM_SMEM>>>(hA, w2t, b2, hB, WID);
    wcvt_kernel<<<(WID * WID + 255) / 256, 256>>>(W3, w3t, WID);

    // enc = relu(h2 @ W3 + b3)
    f16_gemm<0><<<ggrid, 256, GEMM_SMEM>>>(hB, w3t, b3, hA, WID);
    wcvt_kernel<<<(WID * WID + 255) / 256, 256>>>(Wr, wrt, WID);

    // z = enc @ Wr (bias+relu after scan — scan commutes with Wr)
    f16_gemm<1><<<ggrid, 256, GEMM_SMEM>>>(hA, wrt, nullptr, z16, WID);

    segstart_kernel<<<1, NSEG + 1>>>(seg, M);
    weff_kernel<<<(COMB * HEADS + 127) / 128, 128>>>(Wk, Wq);

    // agg = relu(cumseg_mean(z) + br)
    scan_kernel<<<dim3(NSEG, WID / 256), 256>>>(z16, br, agg16);

    // out = [X, agg] @ w_eff / sqrt(DPD)
    final_kernel<<<M / 8, 256>>>(x16, agg16, out, M);
}

// round 17
// speedup vs baseline: 1.2076x; 1.2076x over previous
#include <cuda_runtime.h>
#include <cuda_fp16.h>
#include <cstdint>

// ---------------------------------------------------------------------------
// Problem constants
// ---------------------------------------------------------------------------
#define D_IN   128
#define WID    512
#define NSEG   256
#define HEADS  8
#define DPD    128
#define COMB   (D_IN + WID)
#define RCP_TAB 4096
#define NMAX 131072

// ---------------------------------------------------------------------------
// Device global scratch (no runtime allocation)
// ---------------------------------------------------------------------------
__device__ __half g_x16[(size_t)NMAX * D_IN];
__device__ __half g_hA[(size_t)NMAX * WID];
__device__ __half g_hB[(size_t)NMAX * WID];
__device__ __half g_z16[(size_t)NMAX * WID];
__device__ __half g_agg16[(size_t)NMAX * WID];
__device__ __half g_w1t[WID * D_IN];
__device__ __half g_w2t[WID * WID];
__device__ __half g_w3t[WID * WID];
__device__ __half g_wrt[WID * WID];
__device__ float g_weff[COMB * HEADS];
__device__ int   g_segstart[NSEG + 1];
__device__ float g_rcp[RCP_TAB];

// ---------------------------------------------------------------------------
// PTX primitives (non-arch-specific; valid on plain sm_100)
// ---------------------------------------------------------------------------
__device__ __forceinline__ uint32_t smem_u32(const void* p) {
    uint32_t a;
    asm("{ .reg .u64 t; cvta.to.shared.u64 t, %1; cvt.u32.u64 %0, t; }" : "=r"(a) : "l"(p));
    return a;
}

#define CP_ASYNC16(dst, src) \
    asm volatile("cp.async.cg.shared.global [%0], [%1], 16;" :: "r"(dst), "l"(src))
#define CP_COMMIT() asm volatile("cp.async.commit_group;" ::: "memory")
#define CP_WAIT2()  asm volatile("cp.async.wait_group 2;" ::: "memory")
#define CP_WAIT0()  asm volatile("cp.async.wait_group 0;" ::: "memory")

#define LDSM_X4(r, addr) \
    asm volatile("ldmatrix.sync.aligned.m8n8.x4.shared.b16 {%0,%1,%2,%3}, [%4];" \
        : "=r"((r)[0]), "=r"((r)[1]), "=r"((r)[2]), "=r"((r)[3]) : "r"(addr))

// fp16 MMA m16n8k16, fp32 accum
__device__ __forceinline__ void mma_f16(float* d, const uint32_t* a, uint32_t b0, uint32_t b1) {
    asm volatile(
        "mma.sync.aligned.m16n8k16.row.col.f32.f16.f16.f32 "
        "{%0,%1,%2,%3}, {%4,%5,%6,%7}, {%8,%9}, {%0,%1,%2,%3};"
        : "+f"(d[0]), "+f"(d[1]), "+f"(d[2]), "+f"(d[3])
        : "r"(a[0]), "r"(a[1]), "r"(a[2]), "r"(a[3]), "r"(b0), "r"(b1));
}

// ---------------------------------------------------------------------------
// Small precompute kernels
// ---------------------------------------------------------------------------
__global__ void segstart_kernel(const int* __restrict__ segw, int M) {
    int s = threadIdx.x;
    if (s > NSEG) return;
    bool is64 = (segw[M - 1] == 0);   // int64: high half of last elem is 0
    int lo = 0, hi = M;
    while (lo < hi) {
        int mid = (lo + hi) >> 1;
        int v = is64 ? segw[2 * mid] : segw[mid];
        if (v < s) lo = mid + 1; else hi = mid;
    }
    g_segstart[s] = lo;
}

__global__ void rcp_init_kernel() {
    int i = blockIdx.x * blockDim.x + threadIdx.x;
    if (i < RCP_TAB) g_rcp[i] = 1.0f / (float)(i ? i : 1);
}

__global__ void weff_kernel(const float* __restrict__ Wk, const float* __restrict__ Wq) {
    int idx = blockIdx.x * blockDim.x + threadIdx.x;
    if (idx >= COMB * HEADS) return;
    int j = idx >> 3, h = idx & 7;
    const float* wk = Wk + (size_t)j * (HEADS * DPD) + h * DPD;
    const float* wq = Wq + h * DPD;
    float s = 0.f;
    #pragma unroll 8
    for (int d = 0; d < DPD; d++) s += wk[d] * wq[d];
    g_weff[idx] = s;
}

// X fp32 -> fp16 (vectorized)
__global__ void xcvt_kernel(const float* __restrict__ X, __half* __restrict__ O, size_t n4) {
    size_t i = (size_t)blockIdx.x * blockDim.x + threadIdx.x;
    if (i >= n4) return;
    float4 v = ((const float4*)X)[i];
    ((__half2*)O)[2 * i]     = __floats2half2_rn(v.x, v.y);
    ((__half2*)O)[2 * i + 1] = __floats2half2_rn(v.z, v.w);
}

// W [K, 512] fp32 -> Wt [512, K] fp16 (transpose + convert)
__global__ void wcvt_kernel(const float* __restrict__ W, __half* __restrict__ Wt, int K) {
    int i = blockIdx.x * blockDim.x + threadIdx.x;
    if (i >= WID * K) return;
    int n = i / K, k = i % K;
    Wt[i] = __float2half(W[(size_t)k * WID + n]);
}

// ---------------------------------------------------------------------------
// fp16 GEMM on mma.sync m16n8k16 (fp32 accum) — Round-15 config, deeper ring
//   CTA tile 128x128, 8 warps (4m x 2n), warp tile 32x64, K-chunk 32 elems,
//   4-stage cp.async ring (WAIT2: two chunks of load slack), 2 CTA/SM,
//   B-fragment prefetch across k16 steps, smem-staged coalesced epilogue.
//   MODE 0: Oh = fp16(relu(D + bias)) ; MODE 1: Oh = fp16(D)
// smem rows: 32 fp16 = 64 B padded to TS_B=80 (conflict-free ldsm).
// ---------------------------------------------------------------------------
#define TS_B      80
#define T128_B    (128 * TS_B)              // 10240 per operand tile
#define ST_A      0
#define ST_B      (T128_B)
#define STAGE_B   (2 * T128_B)              // 20480
#define NSTAGE    4
#define GEMM_SMEM (NSTAGE * STAGE_B)        // 81920
#define EPI_STW   136                       // fp16 stride (272 B) for staging

template<int MODE>
__global__ __launch_bounds__(256, 2)
void f16_gemm(const __half* __restrict__ A, const __half* __restrict__ B,
              const float* __restrict__ bias, __half* __restrict__ Oh, int K) {
    extern __shared__ char smem[];
    const uint32_t sb = smem_u32(smem);

    const int tid    = threadIdx.x;
    const int wid    = tid >> 5;
    const int lane   = tid & 31;
    const int warp_m = wid >> 1;          // 0..3 -> m offset 32*warp_m
    const int warp_n = wid & 1;           // 0..1 -> n offset 64*warp_n
    const int m0 = blockIdx.y * 128;      // x fastest -> A panel shared in L2
    const int n0 = blockIdx.x * 128;

    // ---- load setup: 4 cp.async per thread per chunk; ptr += 32 elems ----
    const int lr = tid >> 1;              // 0..127 row
    const int lj = (tid & 1) * 2;         // 16B chunk pair base {0,1} or {2,3}
    const __half* pA = A + (size_t)(m0 + lr) * K + lj * 8;
    const __half* pB = B + (size_t)(n0 + lr) * K + lj * 8;
    const uint32_t dA0 = (uint32_t)(ST_A + lr * TS_B + lj * 16);
    const uint32_t dB0 = (uint32_t)(ST_B + lr * TS_B + lj * 16);

    // ---- compute setup ----
    const int lrow = lane & 15;
    const int lchk = (lane >> 4) * 16;
    const uint32_t aoff = (uint32_t)((warp_m * 32 + lrow) * TS_B + lchk);
    const uint32_t boff = (uint32_t)((warp_n * 64 + lrow) * TS_B + lchk);

    float acc[2][8][4];                   // [mb 16][nb n8][frag]
    #pragma unroll
    for (int i = 0; i < 2; i++)
        #pragma unroll
        for (int j = 0; j < 8; j++)
            #pragma unroll
            for (int q = 0; q < 4; q++) acc[i][j][q] = 0.f;

    const int nch = K >> 5;               // 32-elem chunks

    #define ISSUE_CHUNK(stg) do {                          \
        uint32_t _b = sb + (stg) * STAGE_B;                \
        CP_ASYNC16(_b + dA0,      pA);                     \
        CP_ASYNC16(_b + dA0 + 16, pA + 8);                 \
        CP_ASYNC16(_b + dB0,      pB);                     \
        CP_ASYNC16(_b + dB0 + 16, pB + 8);                 \
        pA += 32; pB += 32;                                \
        CP_COMMIT();                                       \
    } while (0)

    ISSUE_CHUNK(0);
    if (nch > 1) ISSUE_CHUNK(1);
    if (nch > 2) ISSUE_CHUNK(2);

    int stg = 0;
    for (int c = 0; c < nch; c++) {
        if (c + 1 < nch) CP_WAIT2(); else CP_WAIT0();
        __syncthreads();                  // single sync per chunk
        if (c + 3 < nch) {
            int ns = stg + 3; if (ns >= NSTAGE) ns -= NSTAGE;
            ISSUE_CHUNK(ns);
        }

        const uint32_t stage = sb + stg * STAGE_B;
        const uint32_t sA = stage + ST_A + aoff;
        const uint32_t sB_ = stage + ST_B + boff;

        uint32_t bh[4][4], bh2[4][4], af[2][4];
        // ks=0 fragments
        #pragma unroll
        for (int g = 0; g < 4; g++)
            LDSM_X4(bh[g], sB_ + g * (16 * TS_B));
        #pragma unroll
        for (int mb = 0; mb < 2; mb++)
            LDSM_X4(af[mb], sA + mb * (16 * TS_B));
        // prefetch ks=1 B fragments — latency hides under ks=0 MMAs
        #pragma unroll
        for (int g = 0; g < 4; g++)
            LDSM_X4(bh2[g], sB_ + g * (16 * TS_B) + 32);

        // ks=0 MMAs
        #pragma unroll
        for (int mb = 0; mb < 2; mb++)
            #pragma unroll
            for (int nb = 0; nb < 8; nb++) {
                const int g = nb >> 1, p = nb & 1;
                mma_f16(acc[mb][nb], af[mb], bh[g][p], bh[g][p + 2]);
            }

        // ks=1 A fragments (overwrite af) then ks=1 MMAs
        #pragma unroll
        for (int mb = 0; mb < 2; mb++)
            LDSM_X4(af[mb], sA + mb * (16 * TS_B) + 32);
        #pragma unroll
        for (int mb = 0; mb < 2; mb++)
            #pragma unroll
            for (int nb = 0; nb < 8; nb++) {
                const int g = nb >> 1, p = nb & 1;
                mma_f16(acc[mb][nb], af[mb], bh2[g][p], bh2[g][p + 2]);
            }

        if (++stg == NSTAGE) stg = 0;
    }
    #undef ISSUE_CHUNK

    // ---------------- Epilogue (smem-staged, coalesced fp16 stores) --------
    const int gid  = lane >> 2;
    const int tid4 = lane & 3;

    __syncthreads();                      // mainloop done; reuse stage smem
    __half* sh = (__half*)smem;

    #pragma unroll
    for (int nb = 0; nb < 8; nb++) {
        const int cc  = warp_n * 64 + nb * 8 + tid4 * 2;
        const int col = n0 + cc;
        float b0 = 0.f, b1 = 0.f;
        if (MODE == 0) { b0 = bias[col]; b1 = bias[col + 1]; }
        #pragma unroll
        for (int mb = 0; mb < 2; mb++) {
            #pragma unroll
            for (int half = 0; half < 2; half++) {
                const int r = warp_m * 32 + mb * 16 + gid + half * 8;
                float d0 = acc[mb][nb][2 * half];
                float d1 = acc[mb][nb][2 * half + 1];
                if (MODE == 0) {
                    d0 = fmaxf(d0 + b0, 0.f);
                    d1 = fmaxf(d1 + b1, 0.f);
                }
                *(__half2*)(sh + r * EPI_STW + cc) = __floats2half2_rn(d0, d1);
            }
        }
    }
    __syncthreads();

    // copy-out: warp owns 16 rows; per iter 2 rows x 16 chunks of 16B
    const int rhalf = lane >> 4;          // 0..1
    const int c16   = lane & 15;          // 16B chunk in 256B row
    #pragma unroll
    for (int it = 0; it < 8; it++) {
        const int r = wid * 16 + it * 2 + rhalf;
        const uint4 vh = *(const uint4*)(sh + r * EPI_STW + c16 * 8);
        const size_t gbase = (size_t)(m0 + r) * WID + n0 + c16 * 8;
        *(uint4*)(Oh + gbase) = vh;
    }
}

// ---------------------------------------------------------------------------
// Segmented prefix-mean + bias + relu (z fp16 -> agg fp16; fp32 accumulate)
// Unrolled x4: the 4 loads are independent of the running sum -> MLP=4.
// ---------------------------------------------------------------------------
__global__ void scan_kernel(const __half* __restrict__ Z, const float* __restrict__ br,
                            __half* __restrict__ Agg) {
    int seg = blockIdx.x;
    int col = blockIdx.y * blockDim.x + threadIdx.x;
    int s = g_segstart[seg];
    int e = g_segstart[seg + 1];
    float b = br[col];
    float run = 0.f;
    int n = s;
    for (; n + 4 <= e; n += 4) {
        float v0 = __half2float(Z[(size_t)(n    ) * WID + col]);
        float v1 = __half2float(Z[(size_t)(n + 1) * WID + col]);
        float v2 = __half2float(Z[(size_t)(n + 2) * WID + col]);
        float v3 = __half2float(Z[(size_t)(n + 3) * WID + col]);
        float r0 = run + v0;
        float r1 = r0 + v1;
        float r2 = r1 + v2;
        float r3 = r2 + v3;
        int c0 = n - s + 1;
        float m0_ = (c0     < RCP_TAB) ? r0 * g_rcp[c0]     : r0 / (float)(c0);
        float m1_ = (c0 + 1 < RCP_TAB) ? r1 * g_rcp[c0 + 1] : r1 / (float)(c0 + 1);
        float m2_ = (c0 + 2 < RCP_TAB) ? r2 * g_rcp[c0 + 2] : r2 / (float)(c0 + 2);
        float m3_ = (c0 + 3 < RCP_TAB) ? r3 * g_rcp[c0 + 3] : r3 / (float)(c0 + 3);
        Agg[(size_t)(n    ) * WID + col] = __float2half(fmaxf(m0_ + b, 0.f));
        Agg[(size_t)(n + 1) * WID + col] = __float2half(fmaxf(m1_ + b, 0.f));
        Agg[(size_t)(n + 2) * WID + col] = __float2half(fmaxf(m2_ + b, 0.f));
        Agg[(size_t)(n + 3) * WID + col] = __float2half(fmaxf(m3_ + b, 0.f));
        run = r3;
    }
    for (; n < e; n++) {
        run += __half2float(Z[(size_t)n * WID + col]);
        int cnt = n - s + 1;
        float m = (cnt < RCP_TAB) ? run * g_rcp[cnt] : run / (float)cnt;
        Agg[(size_t)n * WID + col] = __float2half(fmaxf(m + b, 0.f));
    }
}

// ---------------------------------------------------------------------------
// Final projection: out[n,h] = ([X, agg] @ w_eff)[n,h] / sqrt(DPD)
// (reads fp16 X and fp16 agg)
// ---------------------------------------------------------------------------
__global__ __launch_bounds__(256)
void final_kernel(const __half* __restrict__ X16, const __half* __restrict__ Agg,
                  float* __restrict__ out, int M) {
    __shared__ float ws[HEADS * COMB];
    for (int i = threadIdx.x; i < COMB * HEADS; i += blockDim.x) {
        int j = i >> 3, h = i & 7;
        ws[h * COMB + j] = g_weff[i];
    }
    __syncthreads();

    int warp = threadIdx.x >> 5;
    int lane = threadIdx.x & 31;
    int row  = blockIdx.x * 8 + warp;
    if (row >= M) return;

    const __half* xr = X16 + (size_t)row * D_IN;
    const __half* ar = Agg + (size_t)row * WID;

    float acc[HEADS];
    #pragma unroll
    for (int h = 0; h < HEADS; h++) acc[h] = 0.f;

    #pragma unroll
    for (int t = 0; t < D_IN / 32; t++) {
        int j = t * 32 + lane;
        float v = __half2float(xr[j]);
        #pragma unroll
        for (int h = 0; h < HEADS; h++) acc[h] = fmaf(v, ws[h * COMB + j], acc[h]);
    }
    #pragma unroll
    for (int t = 0; t < WID / 32; t++) {
        int j = t * 32 + lane;
        float v = __half2float(ar[j]);
        #pragma unroll
        for (int h = 0; h < HEADS; h++) acc[h] = fmaf(v, ws[h * COMB + D_IN + j], acc[h]);
    }

    #pragma unroll
    for (int off = 16; off; off >>= 1)
        #pragma unroll
        for (int h = 0; h < HEADS; h++)
            acc[h] += __shfl_xor_sync(0xffffffffu, acc[h], off);

    if (lane < HEADS)
        out[(size_t)row * HEADS + lane] = acc[lane] * 0.08838834764831844f;
}

// ---------------------------------------------------------------------------
// Launch
// ---------------------------------------------------------------------------
extern "C" void kernel_launch(void* const* d_in, const int* in_sizes, int n_in,
                              void* d_out, int out_size) {
    const float* X   = (const float*)d_in[0];
    const int*   seg = (const int*)  d_in[1];
    const float* W1  = (const float*)d_in[2];
    const float* b1  = (const float*)d_in[3];
    const float* W2  = (const float*)d_in[4];
    const float* b2  = (const float*)d_in[5];
    const float* W3  = (const float*)d_in[6];
    const float* b3  = (const float*)d_in[7];
    const float* Wr  = (const float*)d_in[8];
    const float* br  = (const float*)d_in[9];
    const float* Wk  = (const float*)d_in[10];
    const float* Wq  = (const float*)d_in[11];
    float* out = (float*)d_out;

    const int M = in_sizes[0] / D_IN;

    __half *x16, *hA, *hB, *z16, *agg16, *w1t, *w2t, *w3t, *wrt;
    cudaGetSymbolAddress((void**)&x16, g_x16);
    cudaGetSymbolAddress((void**)&hA,  g_hA);
    cudaGetSymbolAddress((void**)&hB,  g_hB);
    cudaGetSymbolAddress((void**)&z16, g_z16);
    cudaGetSymbolAddress((void**)&agg16, g_agg16);
    cudaGetSymbolAddress((void**)&w1t, g_w1t);
    cudaGetSymbolAddress((void**)&w2t, g_w2t);
    cudaGetSymbolAddress((void**)&w3t, g_w3t);
    cudaGetSymbolAddress((void**)&wrt, g_wrt);

    cudaFuncSetAttribute(f16_gemm<0>, cudaFuncAttributeMaxDynamicSharedMemorySize, GEMM_SMEM);
    cudaFuncSetAttribute(f16_gemm<1>, cudaFuncAttributeMaxDynamicSharedMemorySize, GEMM_SMEM);

    const dim3 ggrid(WID / 128, M / 128);  // x fastest: 4 N-blocks share an A panel

    xcvt_kernel<<<(unsigned)(((size_t)M * D_IN / 4 + 255) / 256), 256>>>(X, x16, (size_t)M * D_IN / 4);
    wcvt_kernel<<<(WID * D_IN + 255) / 256, 256>>>(W1, w1t, D_IN);
    rcp_init_kernel<<<RCP_TAB / 256, 256>>>();

    // h1 = relu(X @ W1 + b1)
    f16_gemm<0><<<ggrid, 256, GEMM_SMEM>>>(x16, w1t, b1, hA, D_IN);
    wcvt_kernel<<<(WID * WID + 255) / 256, 256>>>(W2, w2t, WID);

    // h2 = relu(h1 @ W2 + b2)
    f16_gemm<0><<<ggrid, 256, GEMM_SMEM>>>(hA, w2t, b2, hB, WID);
    wcvt_kernel<<<(WID * WID + 255) / 256, 256>>>(W3, w3t, WID);

    // enc = relu(h2 @ W3 + b3)
    f16_gemm<0><<<ggrid, 256, GEMM_SMEM>>>(hB, w3t, b3, hA, WID);
    wcvt_kernel<<<(WID * WID + 255) / 256, 256>>>(Wr, wrt, WID);

    // z = enc @ Wr (bias+relu after scan — scan commutes with Wr)
    f16_gemm<1><<<ggrid, 256, GEMM_SMEM>>>(hA, wrt, nullptr, z16, WID);

    segstart_kernel<<<1, NSEG + 1>>>(seg, M);
    weff_kernel<<<(COMB * HEADS + 127) / 128, 128>>>(Wk, Wq);

    // agg = relu(cumseg_mean(z) + br)
    scan_kernel<<<dim3(NSEG, WID / 256), 256>>>(z16, br, agg16);

    // out = [X, agg] @ w_eff / sqrt(DPD)
    final_kernel<<<M / 8, 256>>>(x16, agg16, out, M);
}